// round 1
// baseline (speedup 1.0000x reference)
#include <cuda_runtime.h>
#include <cuda_bf16.h>
#include <math.h>

// ---------------- problem constants ----------------
#define BB   2
#define TT   2048
#define DD   1024
#define NHH  16
#define HDD  64
#define FFD  4096
#define NLL  2
#define VV   32000
#define MM   (BB*TT)          // 4096 rows
#define EPSF 1.1920929e-07f

// ---------------- scratch (device globals; no allocation allowed) ------------
__device__ float g_h  [MM * DD];        // residual stream
__device__ float g_n  [MM * DD];        // rmsnorm output
__device__ float g_qkv[MM * 3 * DD];    // qkv projections
__device__ float g_att[MM * DD];        // attention output (B,T,NH,HD) = (M,D)
__device__ float g_fg [MM * FFD];       // gate (then gate*up)
__device__ float g_fu [MM * FFD];       // up

// ---------------- embedding gather ----------------
__global__ void embed_kernel(const int* __restrict__ x,
                             const float* __restrict__ emb,
                             float* __restrict__ h)
{
    int row = blockIdx.x;                 // 0..4095
    int t   = threadIdx.x;                // 0..255 (float4 each)
    int id  = x[row];
    const float4* src = (const float4*)(emb + (size_t)id * DD);
    float4*       dst = (float4*)(h + (size_t)row * DD);
    dst[t] = src[t];
}

// ---------------- RMSNorm (one block per row of 1024) ----------------
__global__ void rmsnorm_kernel(const float* __restrict__ in,
                               const float* __restrict__ w,
                               float* __restrict__ out)
{
    int row = blockIdx.x;
    int t   = threadIdx.x;                // 256 threads, float4 each
    const float4* r4 = (const float4*)(in + (size_t)row * DD);
    float4 v = r4[t];
    float ss = v.x*v.x + v.y*v.y + v.z*v.z + v.w*v.w;
    #pragma unroll
    for (int o = 16; o; o >>= 1) ss += __shfl_xor_sync(0xffffffffu, ss, o);
    __shared__ float red[8];
    if ((t & 31) == 0) red[t >> 5] = ss;
    __syncthreads();
    __shared__ float scale_sh;
    if (t == 0) {
        float s = 0.f;
        #pragma unroll
        for (int i = 0; i < 8; i++) s += red[i];
        scale_sh = rsqrtf(s / (float)DD + EPSF);
    }
    __syncthreads();
    float sc = scale_sh;
    const float4* w4 = (const float4*)w;
    float4 wv = w4[t];
    float4 o4;
    o4.x = v.x * sc * wv.x;
    o4.y = v.y * sc * wv.y;
    o4.z = v.z * sc * wv.z;
    o4.w = v.w * sc * wv.w;
    ((float4*)(out + (size_t)row * DD))[t] = o4;
}

// ---------------- generic SGEMM: C[M,N] = A[M,K] * W[N,K]^T (+bias)(+epi) ----
// EPI: 0 = bias only, 1 = bias + residual add (res), 2 = bias + silu
// Tiles: 128x128x8, 256 threads, 8x8 per thread. All dims multiples of 128/8.
template<int EPI>
__global__ void __launch_bounds__(256, 2)
gemm_nt(const float* __restrict__ A, const float* __restrict__ W,
        const float* __restrict__ bias, const float* __restrict__ res,
        float* __restrict__ C, int M, int N, int K)
{
    __shared__ float As[8][128];
    __shared__ float Bs[8][128];

    const int tid = threadIdx.x;
    const int tm  = tid >> 4;          // 0..15
    const int tn  = tid & 15;          // 0..15
    const int lrow = tid >> 1;         // 0..127 (loader row)
    const int lk   = (tid & 1) << 2;   // 0 or 4

    const float* Ab = A + (size_t)(blockIdx.y * 128) * K;
    const float* Wb = W + (size_t)(blockIdx.x * 128) * K;

    float acc[8][8] = {};

    for (int k0 = 0; k0 < K; k0 += 8) {
        float4 av = *(const float4*)(Ab + (size_t)lrow * K + k0 + lk);
        float4 wv = *(const float4*)(Wb + (size_t)lrow * K + k0 + lk);
        As[lk+0][lrow] = av.x; As[lk+1][lrow] = av.y;
        As[lk+2][lrow] = av.z; As[lk+3][lrow] = av.w;
        Bs[lk+0][lrow] = wv.x; Bs[lk+1][lrow] = wv.y;
        Bs[lk+2][lrow] = wv.z; Bs[lk+3][lrow] = wv.w;
        __syncthreads();
        #pragma unroll
        for (int kk = 0; kk < 8; kk++) {
            float a[8], b[8];
            #pragma unroll
            for (int i = 0; i < 8; i++) a[i] = As[kk][tm*8 + i];
            #pragma unroll
            for (int j = 0; j < 8; j++) b[j] = Bs[kk][tn*8 + j];
            #pragma unroll
            for (int i = 0; i < 8; i++)
                #pragma unroll
                for (int j = 0; j < 8; j++)
                    acc[i][j] += a[i] * b[j];
        }
        __syncthreads();
    }

    const size_t crow0 = (size_t)blockIdx.y * 128 + tm * 8;
    const int    ccol0 = blockIdx.x * 128 + tn * 8;
    #pragma unroll
    for (int i = 0; i < 8; i++) {
        size_t base = (crow0 + i) * (size_t)N + ccol0;
        #pragma unroll
        for (int j = 0; j < 8; j++) {
            float v = acc[i][j];
            if (bias) v += __ldg(bias + ccol0 + j);
            if (EPI == 1) v += res[base + j];
            if (EPI == 2) v = v / (1.f + __expf(-v));
            C[base + j] = v;
        }
    }
}

// ---------------- flash attention (fp32, causal) ----------------
// qkv layout: [B, T, 3, NH, HD]  -> elem ((b*T+t)*3 + s)*D + h*HD + d
// out layout: [B, T, NH, HD]     == [M, D]
// grid: (T/64, B*NH), 256 threads, BQ=BK=64, HD=64.
#define LDSA 68
__global__ void __launch_bounds__(256)
attn_kernel(const float* __restrict__ qkv, float* __restrict__ o)
{
    extern __shared__ float sm[];
    float* Qs = sm;
    float* Ks = Qs + 64 * LDSA;
    float* Vs = Ks + 64 * LDSA;
    float* Ps = Vs + 64 * LDSA;

    const int qb  = blockIdx.x;
    const int bh  = blockIdx.y;
    const int bb  = bh >> 4;          // batch
    const int hh  = bh & 15;          // head
    const int tid = threadIdx.x;
    const int tm  = tid >> 4, tn = tid & 15;
    const int r0  = tm * 4, c0 = tn * 4;

    // load Q tile (64 rows x 64 dims)
    for (int i = tid; i < 64 * 16; i += 256) {
        int r = i >> 4, c4 = (i & 15) << 2;
        size_t gidx = ((size_t)(bb * TT + qb * 64 + r) * 3) * DD + hh * HDD + c4;
        float4 v = *(const float4*)(qkv + gidx);
        float* d = &Qs[r * LDSA + c4];
        d[0] = v.x; d[1] = v.y; d[2] = v.z; d[3] = v.w;
    }

    float accO[4][4] = {};
    float mrow[4] = {-1e30f, -1e30f, -1e30f, -1e30f};
    float lrow[4] = {};

    for (int kb = 0; kb <= qb; kb++) {
        __syncthreads();   // protect Ks/Vs (prev PV reads) and Q (first iter)
        for (int i = tid; i < 64 * 16; i += 256) {
            int r = i >> 4, c4 = (i & 15) << 2;
            size_t base = ((size_t)(bb * TT + kb * 64 + r) * 3) * DD + hh * HDD + c4;
            float4 kv = *(const float4*)(qkv + base + DD);
            float4 vv = *(const float4*)(qkv + base + 2 * DD);
            float* dk = &Ks[r * LDSA + c4];
            float* dv = &Vs[r * LDSA + c4];
            dk[0]=kv.x; dk[1]=kv.y; dk[2]=kv.z; dk[3]=kv.w;
            dv[0]=vv.x; dv[1]=vv.y; dv[2]=vv.z; dv[3]=vv.w;
        }
        __syncthreads();

        // S = Q K^T (4x4 per thread)
        float s[4][4] = {};
        #pragma unroll
        for (int d = 0; d < 64; d += 4) {
            float4 qv[4], kv[4];
            #pragma unroll
            for (int i = 0; i < 4; i++) qv[i] = *(const float4*)&Qs[(r0+i)*LDSA + d];
            #pragma unroll
            for (int j = 0; j < 4; j++) kv[j] = *(const float4*)&Ks[(c0+j)*LDSA + d];
            #pragma unroll
            for (int i = 0; i < 4; i++)
                #pragma unroll
                for (int j = 0; j < 4; j++)
                    s[i][j] += qv[i].x*kv[j].x + qv[i].y*kv[j].y
                             + qv[i].z*kv[j].z + qv[i].w*kv[j].w;
        }
        // scale + causal mask
        #pragma unroll
        for (int i = 0; i < 4; i++) {
            int qi = qb * 64 + r0 + i;
            #pragma unroll
            for (int j = 0; j < 4; j++) {
                int ki = kb * 64 + c0 + j;
                float v = s[i][j] * 0.125f;       // 1/sqrt(64)
                s[i][j] = (ki > qi) ? -1e30f : v;
            }
        }
        // online softmax per row (reduce across the 16 tn-threads)
        #pragma unroll
        for (int i = 0; i < 4; i++) {
            float rm = fmaxf(fmaxf(s[i][0], s[i][1]), fmaxf(s[i][2], s[i][3]));
            #pragma unroll
            for (int off = 8; off; off >>= 1)
                rm = fmaxf(rm, __shfl_xor_sync(0xffffffffu, rm, off));
            float mnew  = fmaxf(mrow[i], rm);
            float alpha = __expf(mrow[i] - mnew);
            mrow[i] = mnew;
            float rs = 0.f;
            #pragma unroll
            for (int j = 0; j < 4; j++) {
                float p = __expf(s[i][j] - mnew);
                s[i][j] = p;
                rs += p;
            }
            #pragma unroll
            for (int off = 8; off; off >>= 1)
                rs += __shfl_xor_sync(0xffffffffu, rs, off);
            lrow[i] = lrow[i] * alpha + rs;
            #pragma unroll
            for (int j = 0; j < 4; j++) accO[i][j] *= alpha;
        }
        // store P to smem
        #pragma unroll
        for (int i = 0; i < 4; i++)
            #pragma unroll
            for (int j = 0; j < 4; j++)
                Ps[(r0+i)*LDSA + c0 + j] = s[i][j];
        __syncthreads();

        // O += P V  (thread owns rows r0..r0+3, cols c0..c0+3)
        #pragma unroll
        for (int jj = 0; jj < 64; jj += 4) {
            float4 pv[4], vv[4];
            #pragma unroll
            for (int i = 0; i < 4; i++) pv[i] = *(const float4*)&Ps[(r0+i)*LDSA + jj];
            #pragma unroll
            for (int t = 0; t < 4; t++) vv[t] = *(const float4*)&Vs[(jj+t)*LDSA + c0];
            #pragma unroll
            for (int i = 0; i < 4; i++) {
                accO[i][0] += pv[i].x*vv[0].x + pv[i].y*vv[1].x + pv[i].z*vv[2].x + pv[i].w*vv[3].x;
                accO[i][1] += pv[i].x*vv[0].y + pv[i].y*vv[1].y + pv[i].z*vv[2].y + pv[i].w*vv[3].y;
                accO[i][2] += pv[i].x*vv[0].z + pv[i].y*vv[1].z + pv[i].z*vv[2].z + pv[i].w*vv[3].z;
                accO[i][3] += pv[i].x*vv[0].w + pv[i].y*vv[1].w + pv[i].z*vv[2].w + pv[i].w*vv[3].w;
            }
        }
    }

    // finalize
    #pragma unroll
    for (int i = 0; i < 4; i++) {
        float inv = 1.f / lrow[i];
        int qi = qb * 64 + r0 + i;
        size_t base = ((size_t)(bb * TT + qi) * NHH + hh) * HDD + c0;
        float4 ov;
        ov.x = accO[i][0] * inv; ov.y = accO[i][1] * inv;
        ov.z = accO[i][2] * inv; ov.w = accO[i][3] * inv;
        *(float4*)(o + base) = ov;
    }
}

// ---------------- elementwise gate *= up ----------------
__global__ void mul_kernel(float* __restrict__ g, const float* __restrict__ u, int n4)
{
    int i = blockIdx.x * blockDim.x + threadIdx.x;
    if (i < n4) {
        float4 a = ((const float4*)g)[i];
        float4 b = ((const float4*)u)[i];
        a.x *= b.x; a.y *= b.y; a.z *= b.z; a.w *= b.w;
        ((float4*)g)[i] = a;
    }
}

// ---------------- launch ----------------
extern "C" void kernel_launch(void* const* d_in, const int* in_sizes, int n_in,
                              void* d_out, int out_size)
{
    const int*   x      = (const int*)  d_in[0];
    const float* emb_w  = (const float*)d_in[1];
    const float* n1_w   = (const float*)d_in[2];
    const float* n2_w   = (const float*)d_in[3];
    const float* qkv_w  = (const float*)d_in[4];
    const float* qkv_b  = (const float*)d_in[5];
    const float* o_w    = (const float*)d_in[6];
    const float* o_b    = (const float*)d_in[7];
    const float* g_w    = (const float*)d_in[8];
    const float* g_b    = (const float*)d_in[9];
    const float* u_w    = (const float*)d_in[10];
    const float* u_b    = (const float*)d_in[11];
    const float* dn_w   = (const float*)d_in[12];
    const float* dn_b   = (const float*)d_in[13];
    const float* norm_w = (const float*)d_in[14];
    const float* head_w = (const float*)d_in[15];
    float* out = (float*)d_out;

    float *h, *n, *qkv, *att, *fg, *fu;
    cudaGetSymbolAddress((void**)&h,   g_h);
    cudaGetSymbolAddress((void**)&n,   g_n);
    cudaGetSymbolAddress((void**)&qkv, g_qkv);
    cudaGetSymbolAddress((void**)&att, g_att);
    cudaGetSymbolAddress((void**)&fg,  g_fg);
    cudaGetSymbolAddress((void**)&fu,  g_fu);

    const int attn_smem = 4 * 64 * LDSA * sizeof(float);   // 69632
    cudaFuncSetAttribute(attn_kernel, cudaFuncAttributeMaxDynamicSharedMemorySize, attn_smem);

    embed_kernel<<<MM, 256>>>(x, emb_w, h);

    for (int l = 0; l < NLL; l++) {
        // attention block
        rmsnorm_kernel<<<MM, 256>>>(h, n1_w + (size_t)l * DD, n);
        gemm_nt<0><<<dim3(3*DD/128, MM/128), 256>>>(
            n, qkv_w + (size_t)l * 3 * DD * DD, qkv_b + (size_t)l * 3 * DD,
            nullptr, qkv, MM, 3*DD, DD);
        attn_kernel<<<dim3(TT/64, BB*NHH), 256, attn_smem>>>(qkv, att);
        gemm_nt<1><<<dim3(DD/128, MM/128), 256>>>(
            att, o_w + (size_t)l * DD * DD, o_b + (size_t)l * DD,
            h, h, MM, DD, DD);
        // FFN block
        rmsnorm_kernel<<<MM, 256>>>(h, n2_w + (size_t)l * DD, n);
        gemm_nt<2><<<dim3(FFD/128, MM/128), 256>>>(
            n, g_w + (size_t)l * FFD * DD, g_b + (size_t)l * FFD,
            nullptr, fg, MM, FFD, DD);
        gemm_nt<0><<<dim3(FFD/128, MM/128), 256>>>(
            n, u_w + (size_t)l * FFD * DD, u_b + (size_t)l * FFD,
            nullptr, fu, MM, FFD, DD);
        mul_kernel<<<(MM*FFD/4 + 255)/256, 256>>>(fg, fu, MM*FFD/4);
        gemm_nt<1><<<dim3(DD/128, MM/128), 256>>>(
            fg, dn_w + (size_t)l * DD * FFD, dn_b + (size_t)l * DD,
            h, h, MM, DD, FFD);
    }

    rmsnorm_kernel<<<MM, 256>>>(h, norm_w, n);
    gemm_nt<0><<<dim3(VV/128, MM/128), 256>>>(
        n, head_w, nullptr, nullptr, out, MM, VV, DD);
}

// round 6
// speedup vs baseline: 2.8599x; 2.8599x over previous
#include <cuda_runtime.h>
#include <cuda_bf16.h>
#include <math.h>
#include <stdint.h>

// ---------------- problem constants ----------------
#define BB   2
#define TT   2048
#define DD   1024
#define NHH  16
#define HDD  64
#define FFD  4096
#define NLL  2
#define VV   32000
#define MM   (BB*TT)          // 4096 rows
#define EPSF 1.1920929e-07f

// ---------------- scratch (device globals; no allocation allowed) ------------
__device__ float g_h  [MM * DD];        // residual stream
__device__ float g_n  [MM * DD];        // rmsnorm output (tf32-rounded)
__device__ float g_qkv[MM * 3 * DD];    // qkv projections
__device__ float g_att[MM * DD];        // attention output (tf32-rounded)
__device__ float g_fg [MM * FFD];       // gate (then gate*up, tf32-rounded)
__device__ float g_fu [MM * FFD];       // up
__device__ float g_wr [VV * DD];        // tf32-rounded weights (max = head W)

// ---------------- small helpers ----------------
__device__ __forceinline__ uint32_t s2u(const void* p) {
    uint32_t a;
    asm("{ .reg .u64 t; cvta.to.shared.u64 t, %1; cvt.u32.u64 %0, t; }" : "=r"(a) : "l"(p));
    return a;
}
__device__ __forceinline__ float tf32r(float x) {
    uint32_t u;
    asm("cvt.rna.tf32.f32 %0, %1;" : "=r"(u) : "f"(x));
    return __uint_as_float(u);
}
__device__ __forceinline__ void cp16(float* dst, const float* src) {
    uint32_t d = s2u(dst);
    asm volatile("cp.async.cg.shared.global [%0], [%1], 16;" :: "r"(d), "l"(src));
}
__device__ __forceinline__ void mma8(float* c, const uint32_t* a, const uint32_t* b) {
    asm volatile(
        "mma.sync.aligned.m16n8k8.row.col.f32.tf32.tf32.f32 "
        "{%0,%1,%2,%3}, {%4,%5,%6,%7}, {%8,%9}, {%0,%1,%2,%3};"
        : "+f"(c[0]), "+f"(c[1]), "+f"(c[2]), "+f"(c[3])
        : "r"(a[0]), "r"(a[1]), "r"(a[2]), "r"(a[3]), "r"(b[0]), "r"(b[1]));
}

// ---------------- embedding gather ----------------
__global__ void embed_kernel(const int* __restrict__ x,
                             const float* __restrict__ emb,
                             float* __restrict__ h)
{
    int row = blockIdx.x;
    int t   = threadIdx.x;                // 256 threads, float4 each
    int id  = x[row];
    const float4* src = (const float4*)(emb + (size_t)id * DD);
    float4*       dst = (float4*)(h + (size_t)row * DD);
    dst[t] = src[t];
}

// ---------------- RMSNorm (one block per row of 1024), tf32-rounded output ---
__global__ void rmsnorm_kernel(const float* __restrict__ in,
                               const float* __restrict__ w,
                               float* __restrict__ out)
{
    int row = blockIdx.x;
    int t   = threadIdx.x;
    const float4* r4 = (const float4*)(in + (size_t)row * DD);
    float4 v = r4[t];
    float ss = v.x*v.x + v.y*v.y + v.z*v.z + v.w*v.w;
    #pragma unroll
    for (int o = 16; o; o >>= 1) ss += __shfl_xor_sync(0xffffffffu, ss, o);
    __shared__ float red[8];
    if ((t & 31) == 0) red[t >> 5] = ss;
    __syncthreads();
    __shared__ float scale_sh;
    if (t == 0) {
        float s = 0.f;
        #pragma unroll
        for (int i = 0; i < 8; i++) s += red[i];
        scale_sh = rsqrtf(s / (float)DD + EPSF);
    }
    __syncthreads();
    float sc = scale_sh;
    const float4* w4 = (const float4*)w;
    float4 wv = w4[t];
    float4 o4;
    o4.x = tf32r(v.x * sc * wv.x);
    o4.y = tf32r(v.y * sc * wv.y);
    o4.z = tf32r(v.z * sc * wv.z);
    o4.w = tf32r(v.w * sc * wv.w);
    ((float4*)(out + (size_t)row * DD))[t] = o4;
}

// ---------------- weight tf32-round pass ----------------
__global__ void wround_kernel(const float* __restrict__ in, float* __restrict__ out, int n4)
{
    int i = blockIdx.x * blockDim.x + threadIdx.x;
    if (i < n4) {
        float4 v = ((const float4*)in)[i];
        v.x = tf32r(v.x); v.y = tf32r(v.y); v.z = tf32r(v.z); v.w = tf32r(v.w);
        ((float4*)out)[i] = v;
    }
}

// ---------------- elementwise gate = tf32r(gate * up) ----------------
__global__ void mul_kernel(float* __restrict__ g, const float* __restrict__ u, int n4)
{
    int i = blockIdx.x * blockDim.x + threadIdx.x;
    if (i < n4) {
        float4 a = ((const float4*)g)[i];
        float4 b = ((const float4*)u)[i];
        a.x = tf32r(a.x * b.x); a.y = tf32r(a.y * b.y);
        a.z = tf32r(a.z * b.z); a.w = tf32r(a.w * b.w);
        ((float4*)g)[i] = a;
    }
}

// ============================================================================
// TF32 mma.sync GEMM: C[M,N] = A[M,K] * W[N,K]^T (+bias)(+epi)
// CTA tile 128x128, K-chunk 32, 3-stage cp.async pipeline, 8 warps (4x2),
// warp tile 32(M)x64(N), mma.m16n8k8.tf32, fp32 accum in registers.
// EPI: 0 = bias only, 1 = bias + residual, 2 = bias + silu
// ============================================================================
#define GSTRIDE     36                          // floats per smem row (128B + 16B pad)
#define STG_FLOATS  (2 * 128 * GSTRIDE)         // A tile + B tile per stage = 9216
#define GEMM_SMEM   (3 * STG_FLOATS * 4)        // 110592 bytes

template<int EPI>
__global__ void __launch_bounds__(256, 2)
gemm_mma(const float* __restrict__ A, const float* __restrict__ W,
         const float* __restrict__ bias, const float* __restrict__ res,
         float* __restrict__ C, int N, int K)
{
    extern __shared__ float sm[];
    const int tid  = threadIdx.x;
    const int wid  = tid >> 5;
    const int lane = tid & 31;
    const int g    = lane >> 2;     // 0..7
    const int t    = lane & 3;      // 0..3
    const int wm   = (wid >> 1) * 32;   // warp M offset in tile
    const int wn   = (wid & 1) * 64;    // warp N offset in tile

    const float* Ag = A + (size_t)blockIdx.y * 128 * K;
    const float* Wg = W + (size_t)blockIdx.x * 128 * K;
    const int NC = K >> 5;              // chunks of K=32

    auto fill = [&](int c) {
        float* as = sm + (c % 3) * STG_FLOATS;
        float* bs = as + 128 * GSTRIDE;
        const float* ag = Ag + c * 32;
        const float* wg = Wg + c * 32;
        #pragma unroll
        for (int i = 0; i < 4; i++) {
            int lin = tid + i * 256;       // 0..1023
            int r   = lin >> 3;            // row 0..127
            int q   = lin & 7;             // float4 index 0..7
            cp16(as + r * GSTRIDE + q * 4, ag + (size_t)r * K + q * 4);
            cp16(bs + r * GSTRIDE + q * 4, wg + (size_t)r * K + q * 4);
        }
    };

    float acc[2][8][4] = {};

    fill(0); asm volatile("cp.async.commit_group;" ::: "memory");
    fill(1); asm volatile("cp.async.commit_group;" ::: "memory");

    for (int c = 0; c < NC; c++) {
        asm volatile("cp.async.wait_group 1;" ::: "memory");
        __syncthreads();
        if (c + 2 < NC) fill(c + 2);
        asm volatile("cp.async.commit_group;" ::: "memory");

        const float* as = sm + (c % 3) * STG_FLOATS;
        const float* bs = as + 128 * GSTRIDE;
        #pragma unroll
        for (int kk = 0; kk < 4; kk++) {
            const int k0 = kk * 8;
            uint32_t af[2][4], bf[8][2];
            #pragma unroll
            for (int mt = 0; mt < 2; mt++) {
                const float* ab = as + (wm + mt * 16) * GSTRIDE + k0;
                af[mt][0] = __float_as_uint(ab[ g      * GSTRIDE + t    ]);
                af[mt][1] = __float_as_uint(ab[(g + 8) * GSTRIDE + t    ]);
                af[mt][2] = __float_as_uint(ab[ g      * GSTRIDE + t + 4]);
                af[mt][3] = __float_as_uint(ab[(g + 8) * GSTRIDE + t + 4]);
            }
            #pragma unroll
            for (int nt = 0; nt < 8; nt++) {
                const float* bb = bs + (wn + nt * 8 + g) * GSTRIDE + k0;
                bf[nt][0] = __float_as_uint(bb[t]);
                bf[nt][1] = __float_as_uint(bb[t + 4]);
            }
            #pragma unroll
            for (int mt = 0; mt < 2; mt++)
                #pragma unroll
                for (int nt = 0; nt < 8; nt++)
                    mma8(acc[mt][nt], af[mt], bf[nt]);
        }
    }

    // ---- epilogue: register accumulators -> C with bias / residual / silu ----
    const size_t rbase = (size_t)blockIdx.y * 128 + wm;
    const int    cbase = blockIdx.x * 128 + wn;
    #pragma unroll
    for (int mt = 0; mt < 2; mt++) {
        #pragma unroll
        for (int half = 0; half < 2; half++) {       // c0,c1 (row g) / c2,c3 (row g+8)
            size_t row = rbase + mt * 16 + half * 8 + g;
            size_t rowoff = row * (size_t)N;
            #pragma unroll
            for (int nt = 0; nt < 8; nt++) {
                int col = cbase + nt * 8 + 2 * t;
                float v0 = acc[mt][nt][half * 2 + 0];
                float v1 = acc[mt][nt][half * 2 + 1];
                if (bias) {
                    v0 += __ldg(bias + col);
                    v1 += __ldg(bias + col + 1);
                }
                if (EPI == 1) {
                    float2 rv = *(const float2*)(res + rowoff + col);
                    v0 += rv.x; v1 += rv.y;
                }
                if (EPI == 2) {
                    v0 = v0 / (1.f + __expf(-v0));
                    v1 = v1 / (1.f + __expf(-v1));
                }
                float2 ov; ov.x = v0; ov.y = v1;
                *(float2*)(C + rowoff + col) = ov;
            }
        }
    }
}

// ---------------- flash attention (fp32, causal), tf32-rounded outputs -------
#define LDSA 68
__global__ void __launch_bounds__(256)
attn_kernel(const float* __restrict__ qkv, float* __restrict__ o)
{
    extern __shared__ float smf[];
    float* Qs = smf;
    float* Ks = Qs + 64 * LDSA;
    float* Vs = Ks + 64 * LDSA;
    float* Ps = Vs + 64 * LDSA;

    const int qb  = blockIdx.x;
    const int bh  = blockIdx.y;
    const int bb  = bh >> 4;
    const int hh  = bh & 15;
    const int tid = threadIdx.x;
    const int tm  = tid >> 4, tn = tid & 15;
    const int r0  = tm * 4, c0 = tn * 4;

    for (int i = tid; i < 64 * 16; i += 256) {
        int r = i >> 4, c4 = (i & 15) << 2;
        size_t gidx = ((size_t)(bb * TT + qb * 64 + r) * 3) * DD + hh * HDD + c4;
        float4 v = *(const float4*)(qkv + gidx);
        float* d = &Qs[r * LDSA + c4];
        d[0] = v.x; d[1] = v.y; d[2] = v.z; d[3] = v.w;
    }

    float accO[4][4] = {};
    float mrow[4] = {-1e30f, -1e30f, -1e30f, -1e30f};
    float lrow[4] = {};

    for (int kb = 0; kb <= qb; kb++) {
        __syncthreads();
        for (int i = tid; i < 64 * 16; i += 256) {
            int r = i >> 4, c4 = (i & 15) << 2;
            size_t base = ((size_t)(bb * TT + kb * 64 + r) * 3) * DD + hh * HDD + c4;
            float4 kv = *(const float4*)(qkv + base + DD);
            float4 vv = *(const float4*)(qkv + base + 2 * DD);
            float* dk = &Ks[r * LDSA + c4];
            float* dv = &Vs[r * LDSA + c4];
            dk[0]=kv.x; dk[1]=kv.y; dk[2]=kv.z; dk[3]=kv.w;
            dv[0]=vv.x; dv[1]=vv.y; dv[2]=vv.z; dv[3]=vv.w;
        }
        __syncthreads();

        float s[4][4] = {};
        #pragma unroll
        for (int d = 0; d < 64; d += 4) {
            float4 qv[4], kv[4];
            #pragma unroll
            for (int i = 0; i < 4; i++) qv[i] = *(const float4*)&Qs[(r0+i)*LDSA + d];
            #pragma unroll
            for (int j = 0; j < 4; j++) kv[j] = *(const float4*)&Ks[(c0+j)*LDSA + d];
            #pragma unroll
            for (int i = 0; i < 4; i++)
                #pragma unroll
                for (int j = 0; j < 4; j++)
                    s[i][j] += qv[i].x*kv[j].x + qv[i].y*kv[j].y
                             + qv[i].z*kv[j].z + qv[i].w*kv[j].w;
        }
        #pragma unroll
        for (int i = 0; i < 4; i++) {
            int qi = qb * 64 + r0 + i;
            #pragma unroll
            for (int j = 0; j < 4; j++) {
                int ki = kb * 64 + c0 + j;
                float v = s[i][j] * 0.125f;
                s[i][j] = (ki > qi) ? -1e30f : v;
            }
        }
        #pragma unroll
        for (int i = 0; i < 4; i++) {
            float rm = fmaxf(fmaxf(s[i][0], s[i][1]), fmaxf(s[i][2], s[i][3]));
            #pragma unroll
            for (int off = 8; off; off >>= 1)
                rm = fmaxf(rm, __shfl_xor_sync(0xffffffffu, rm, off));
            float mnew  = fmaxf(mrow[i], rm);
            float alpha = __expf(mrow[i] - mnew);
            mrow[i] = mnew;
            float rs = 0.f;
            #pragma unroll
            for (int j = 0; j < 4; j++) {
                float p = __expf(s[i][j] - mnew);
                s[i][j] = p;
                rs += p;
            }
            #pragma unroll
            for (int off = 8; off; off >>= 1)
                rs += __shfl_xor_sync(0xffffffffu, rs, off);
            lrow[i] = lrow[i] * alpha + rs;
            #pragma unroll
            for (int j = 0; j < 4; j++) accO[i][j] *= alpha;
        }
        #pragma unroll
        for (int i = 0; i < 4; i++)
            #pragma unroll
            for (int j = 0; j < 4; j++)
                Ps[(r0+i)*LDSA + c0 + j] = s[i][j];
        __syncthreads();

        #pragma unroll
        for (int jj = 0; jj < 64; jj += 4) {
            float4 pv[4], vv[4];
            #pragma unroll
            for (int i = 0; i < 4; i++) pv[i] = *(const float4*)&Ps[(r0+i)*LDSA + jj];
            #pragma unroll
            for (int tt = 0; tt < 4; tt++) vv[tt] = *(const float4*)&Vs[(jj+tt)*LDSA + c0];
            #pragma unroll
            for (int i = 0; i < 4; i++) {
                accO[i][0] += pv[i].x*vv[0].x + pv[i].y*vv[1].x + pv[i].z*vv[2].x + pv[i].w*vv[3].x;
                accO[i][1] += pv[i].x*vv[0].y + pv[i].y*vv[1].y + pv[i].z*vv[2].y + pv[i].w*vv[3].y;
                accO[i][2] += pv[i].x*vv[0].z + pv[i].y*vv[1].z + pv[i].z*vv[2].z + pv[i].w*vv[3].z;
                accO[i][3] += pv[i].x*vv[0].w + pv[i].y*vv[1].w + pv[i].z*vv[2].w + pv[i].w*vv[3].w;
            }
        }
    }

    #pragma unroll
    for (int i = 0; i < 4; i++) {
        float inv = 1.f / lrow[i];
        int qi = qb * 64 + r0 + i;
        size_t base = ((size_t)(bb * TT + qi) * NHH + hh) * HDD + c0;
        float4 ov;
        ov.x = tf32r(accO[i][0] * inv); ov.y = tf32r(accO[i][1] * inv);
        ov.z = tf32r(accO[i][2] * inv); ov.w = tf32r(accO[i][3] * inv);
        *(float4*)(o + base) = ov;
    }
}

// ---------------- launch ----------------
extern "C" void kernel_launch(void* const* d_in, const int* in_sizes, int n_in,
                              void* d_out, int out_size)
{
    const int*   x      = (const int*)  d_in[0];
    const float* emb_w  = (const float*)d_in[1];
    const float* n1_w   = (const float*)d_in[2];
    const float* n2_w   = (const float*)d_in[3];
    const float* qkv_w  = (const float*)d_in[4];
    const float* qkv_b  = (const float*)d_in[5];
    const float* o_w    = (const float*)d_in[6];
    const float* o_b    = (const float*)d_in[7];
    const float* g_w    = (const float*)d_in[8];
    const float* g_b    = (const float*)d_in[9];
    const float* u_w    = (const float*)d_in[10];
    const float* u_b    = (const float*)d_in[11];
    const float* dn_w   = (const float*)d_in[12];
    const float* dn_b   = (const float*)d_in[13];
    const float* norm_w = (const float*)d_in[14];
    const float* head_w = (const float*)d_in[15];
    float* out = (float*)d_out;

    float *h, *n, *qkv, *att, *fg, *fu, *wr;
    cudaGetSymbolAddress((void**)&h,   g_h);
    cudaGetSymbolAddress((void**)&n,   g_n);
    cudaGetSymbolAddress((void**)&qkv, g_qkv);
    cudaGetSymbolAddress((void**)&att, g_att);
    cudaGetSymbolAddress((void**)&fg,  g_fg);
    cudaGetSymbolAddress((void**)&fu,  g_fu);
    cudaGetSymbolAddress((void**)&wr,  g_wr);

    const int attn_smem = 4 * 64 * LDSA * sizeof(float);
    cudaFuncSetAttribute(attn_kernel, cudaFuncAttributeMaxDynamicSharedMemorySize, attn_smem);
    cudaFuncSetAttribute(gemm_mma<0>, cudaFuncAttributeMaxDynamicSharedMemorySize, GEMM_SMEM);
    cudaFuncSetAttribute(gemm_mma<1>, cudaFuncAttributeMaxDynamicSharedMemorySize, GEMM_SMEM);
    cudaFuncSetAttribute(gemm_mma<2>, cudaFuncAttributeMaxDynamicSharedMemorySize, GEMM_SMEM);

    auto wround = [&](const float* w, int elems) {
        int n4 = elems >> 2;
        wround_kernel<<<(n4 + 255) / 256, 256>>>(w, wr, n4);
    };

    embed_kernel<<<MM, 256>>>(x, emb_w, h);

    for (int l = 0; l < NLL; l++) {
        // ---- attention block ----
        rmsnorm_kernel<<<MM, 256>>>(h, n1_w + (size_t)l * DD, n);
        wround(qkv_w + (size_t)l * 3 * DD * DD, 3 * DD * DD);
        gemm_mma<0><<<dim3(3*DD/128, MM/128), 256, GEMM_SMEM>>>(
            n, wr, qkv_b + (size_t)l * 3 * DD, nullptr, qkv, 3*DD, DD);
        attn_kernel<<<dim3(TT/64, BB*NHH), 256, attn_smem>>>(qkv, att);
        wround(o_w + (size_t)l * DD * DD, DD * DD);
        gemm_mma<1><<<dim3(DD/128, MM/128), 256, GEMM_SMEM>>>(
            att, wr, o_b + (size_t)l * DD, h, h, DD, DD);
        // ---- FFN block ----
        rmsnorm_kernel<<<MM, 256>>>(h, n2_w + (size_t)l * DD, n);
        wround(g_w + (size_t)l * FFD * DD, FFD * DD);
        gemm_mma<2><<<dim3(FFD/128, MM/128), 256, GEMM_SMEM>>>(
            n, wr, g_b + (size_t)l * FFD, nullptr, fg, FFD, DD);
        wround(u_w + (size_t)l * FFD * DD, FFD * DD);
        gemm_mma<0><<<dim3(FFD/128, MM/128), 256, GEMM_SMEM>>>(
            n, wr, u_b + (size_t)l * FFD, nullptr, fu, FFD, DD);
        mul_kernel<<<(MM*FFD/4 + 255)/256, 256>>>(fg, fu, MM*FFD/4);
        wround(dn_w + (size_t)l * DD * FFD, DD * FFD);
        gemm_mma<1><<<dim3(DD/128, MM/128), 256, GEMM_SMEM>>>(
            fg, wr, dn_b + (size_t)l * DD, h, h, DD, FFD);
    }

    rmsnorm_kernel<<<MM, 256>>>(h, norm_w, n);
    wround(head_w, VV * DD);
    gemm_mma<0><<<dim3(VV/128, MM/128), 256, GEMM_SMEM>>>(
        n, wr, nullptr, nullptr, out, VV, DD);
}